// round 13
// baseline (speedup 1.0000x reference)
#include <cuda_runtime.h>
#include <cuda_fp16.h>
#include <cstdint>

// Two-kernel split, lean main:
// prep:  EwT[n][w], EhT[n][h], act fp16 tables in global — 1M exps ONCE.
// main:  corr[b,n] = (1/16384) * sum_h EhT[n,h] * (sum_w EwT[n,w]*act[b,h,w])
//        CTA (n-tile 64, batch b), grid 512, 256 thr, 3 CTAs/SM.
//        cp.async staging only; GEMM mma.sync.m16n8k16.f16; smem epilogue.

#define HDIM 128
#define NPTS 4096

__device__ __align__(256) __half g_A[NPTS * HDIM];       // EwT [n][w]
__device__ __align__(256) __half g_E[NPTS * HDIM];       // EhT [n][h] (unscaled)
__device__ __align__(256) __half g_act[8 * HDIM * HDIM]; // act [b][h][w]

__device__ __forceinline__ uint32_t smem_to_u32(const void* p) {
    uint32_t a;
    asm("{ .reg .u64 t; cvta.to.shared.u64 t, %1; cvt.u32.u64 %0, t; }" : "=r"(a) : "l"(p));
    return a;
}
#define CP16(dst, src) \
    asm volatile("cp.async.cg.shared.global [%0], [%1], 16;" :: "r"(dst), "l"(src) : "memory")
#define CP_COMMIT() asm volatile("cp.async.commit_group;" ::: "memory")
#define CP_WAIT0()  asm volatile("cp.async.wait_group 0;" ::: "memory")

#define LDSM_X4(r0, r1, r2, r3, addr)                                          \
    asm volatile("ldmatrix.sync.aligned.m8n8.x4.shared.b16 {%0,%1,%2,%3}, [%4];" \
        : "=r"(r0), "=r"(r1), "=r"(r2), "=r"(r3) : "r"(addr))

#define MMA_F16(c, a, b0, b1)                                                  \
    asm volatile("mma.sync.aligned.m16n8k16.row.col.f32.f16.f16.f32 "           \
        "{%0,%1,%2,%3},{%4,%5,%6,%7},{%8,%9},{%0,%1,%2,%3};"                    \
        : "+f"((c)[0]), "+f"((c)[1]), "+f"((c)[2]), "+f"((c)[3])                \
        : "r"((a)[0]), "r"((a)[1]), "r"((a)[2]), "r"((a)[3]), "r"(b0), "r"(b1))

// ---------------------------------------------------------------------------
// Kernel 1: fp16 factor tables + act conversion. idx -> (n=idx>>7, j=idx&127).
// ---------------------------------------------------------------------------
__global__ __launch_bounds__(256) void prep_kernel(
    const float* __restrict__ act, const float* __restrict__ mu,
    const float* __restrict__ sigma)
{
    const int idx = blockIdx.x * 256 + threadIdx.x;   // 0 .. 524287
    const int n = idx >> 7;
    const int j = idx & 127;
    const float g = (float)j * (1.0f / 128.0f);

    const float2 m = ((const float2*)mu)[n];
    const float2 s = ((const float2*)sigma)[n];

    const float dy = g - m.y;
    g_A[idx] = __float2half_rn(__expf(-(dy * dy / (2.0f * s.y * s.y))));
    const float dx = g - m.x;
    g_E[idx] = __float2half_rn(__expf(-(dx * dx / (2.0f * s.x * s.x))));

    if (idx < 8 * HDIM * HDIM)
        g_act[idx] = __float2half_rn(act[idx]);
}

// ---------------------------------------------------------------------------
// Kernel 2: lean GEMM + smem epilogue.
// Grid (64 n-tiles, 8 b), 256 thr = 8 warps: wm = wid&1 (n half of 32),
// wn = wid>>1 (h quarter of 32). Rows padded to 272B -> ldmatrix and
// epilogue LDS both conflict-free.
// Each smem row = 128 halves = 256 B = 16 chunks of 16 B.
// ---------------------------------------------------------------------------
#define NSTRIDE  272
#define EW_OFF   0
#define EH_OFF   17408                 // 64*272
#define ACT_OFF  34816                 // +64*272
#define RED_OFF  69632                 // +128*272
#define SMEM_REQ 70656                 // +4*256

__global__ __launch_bounds__(256, 3) void corr_main_kernel(float* __restrict__ out)
{
    extern __shared__ char smem[];
    const uint32_t sb = smem_to_u32(smem);

    const int tid = threadIdx.x;
    const int wid = tid >> 5, l = tid & 31;
    const int wm = wid & 1;            // n half: rows wm*32..+32
    const int wn = wid >> 1;           // h quarter: cols wn*32..+32
    const int b  = blockIdx.y;
    const int n0 = blockIdx.x * 64;

    // ---- Stage EwT (64 rows), EhT (64 rows), act (128 rows) via cp.async --
    // 16 chunks of 16B per row (FULL 256B rows).
    const __half* gW = g_A + n0 * HDIM;
    const __half* gH = g_E + n0 * HDIM;
    const __half* gB = g_act + b * HDIM * HDIM;
    #pragma unroll
    for (int i = tid; i < 1024; i += 256) {    // 4 iters: EW + EH (64 rows x 16)
        const int r = i >> 4, u = i & 15;
        const uint32_t d = r * NSTRIDE + u * 16;
        const int so = r * HDIM + u * 8;
        CP16(sb + EW_OFF + d, gW + so);
        CP16(sb + EH_OFF + d, gH + so);
    }
    #pragma unroll
    for (int i = tid; i < 2048; i += 256) {    // 8 iters: ACT (128 rows x 16)
        const int r = i >> 4, u = i & 15;
        CP16(sb + ACT_OFF + r * NSTRIDE + u * 16, gB + r * HDIM + u * 8);
    }
    CP_COMMIT();
    CP_WAIT0();
    __syncthreads();

    // ---- GEMM: M=64 N=128 K=128, warp tile 32n x 32h ----------------------
    const uint32_t lrow = l & 15, lcol = (l >> 4) * 16;
    const uint32_t aBase = sb + EW_OFF + (wm * 32 + lrow) * NSTRIDE + lcol;
    const uint32_t bBase = sb + ACT_OFF + (wn * 32 + lrow) * NSTRIDE + lcol;

    float acc[2][4][4];
    #pragma unroll
    for (int mt = 0; mt < 2; mt++)
        #pragma unroll
        for (int nt = 0; nt < 4; nt++)
            #pragma unroll
            for (int k = 0; k < 4; k++) acc[mt][nt][k] = 0.0f;

    #pragma unroll
    for (int ks = 0; ks < 8; ks++) {
        const uint32_t koff = ks * 32;
        uint32_t ah[2][4], bv[2][4];
        #pragma unroll
        for (int mt = 0; mt < 2; mt++)
            LDSM_X4(ah[mt][0], ah[mt][1], ah[mt][2], ah[mt][3],
                    aBase + mt * (16 * NSTRIDE) + koff);
        #pragma unroll
        for (int p = 0; p < 2; p++)
            LDSM_X4(bv[p][0], bv[p][1], bv[p][2], bv[p][3],
                    bBase + p * (16 * NSTRIDE) + koff);
        #pragma unroll
        for (int mt = 0; mt < 2; mt++)
            #pragma unroll
            for (int p = 0; p < 2; p++) {
                MMA_F16(acc[mt][2 * p],     ah[mt], bv[p][0], bv[p][2]);
                MMA_F16(acc[mt][2 * p + 1], ah[mt], bv[p][1], bv[p][3]);
            }
    }

    // ---- Epilogue: EhT from smem (conflict-free), quad shuffle, reduce ----
    // D rows: nloc = wm*32 + mt*16 + rh*8 + l/4; cols h = wn*32 + nt*8 + 2(l&3)+{0,1}
    float rowsum[2][2];
    #pragma unroll
    for (int mt = 0; mt < 2; mt++)
        #pragma unroll
        for (int rh = 0; rh < 2; rh++) {
            const int nloc = wm * 32 + mt * 16 + rh * 8 + (l >> 2);
            const char* eRow = smem + EH_OFF + nloc * NSTRIDE
                             + (wn * 32 + 2 * (l & 3)) * 2;
            float s = 0.0f;
            #pragma unroll
            for (int nt = 0; nt < 4; nt++) {
                const float2 ef = __half22float2(*(const __half2*)(eRow + nt * 16));
                s += acc[mt][nt][rh * 2] * ef.x + acc[mt][nt][rh * 2 + 1] * ef.y;
            }
            s += __shfl_xor_sync(0xFFFFFFFF, s, 1);
            s += __shfl_xor_sync(0xFFFFFFFF, s, 2);
            rowsum[mt][rh] = s;
        }

    float* red = (float*)(smem + RED_OFF);      // [4 wn][64 n]
    if ((l & 3) == 0) {
        #pragma unroll
        for (int mt = 0; mt < 2; mt++)
            #pragma unroll
            for (int rh = 0; rh < 2; rh++) {
                const int nloc = wm * 32 + mt * 16 + rh * 8 + (l >> 2);
                red[wn * 64 + nloc] = rowsum[mt][rh];
            }
    }
    __syncthreads();
    if (tid < 64)
        out[b * NPTS + n0 + tid] =
            (red[tid] + red[64 + tid] + red[128 + tid] + red[192 + tid])
            * 6.103515625e-05f;   // 1/16384
}

// ---------------------------------------------------------------------------
extern "C" void kernel_launch(void* const* d_in, const int* in_sizes, int n_in,
                              void* d_out, int out_size)
{
    const float* act   = (const float*)d_in[0];   // [8,128,128]
    const float* mu    = (const float*)d_in[1];   // [4096,2]
    const float* sigma = (const float*)d_in[2];   // [4096,2]
    float* out = (float*)d_out;                   // [8,64,64]

    cudaFuncSetAttribute(corr_main_kernel,
                         cudaFuncAttributeMaxDynamicSharedMemorySize, SMEM_REQ);

    prep_kernel<<<(NPTS * HDIM) / 256, 256>>>(act, mu, sigma);
    corr_main_kernel<<<dim3(NPTS / 64, 8), 256, SMEM_REQ>>>(out);
}

// round 14
// speedup vs baseline: 1.1598x; 1.1598x over previous
#include <cuda_runtime.h>
#include <cuda_fp16.h>
#include <cstdint>

// Single fused kernel, batch-paired, MMA-overlapped staging:
// corr[b,n] = (1/16384) * sum_h EhT[n,h] * ( sum_w EwT[n,w] * act[b,h,w] )
// CTA = (n-tile 64, batch pair b0,b0+1). Grid 64x4 = 256 CTAs @ 2/SM (1 wave).
//   Phase A: act0 LDG->fp16 smem; EwT/EhT fp16 tables via __expf (amortized 2x)
//   Phase B: GEMM0 (M=64 N=128 K=128 fp16 mma) with act1 staging interleaved
//            into the ks loop (LDG latency hidden under tensor work)
//   Phase C: epilogue0 (EhT from smem, quad shuffle, smem reduce)
//   Phase D: GEMM1 over act1;  Phase E: epilogue1

#define HDIM 128
#define NPTS 4096

#define NSTRIDE  272                   // 17*16 -> conflict-free ldmatrix/LDS
#define EW_OFF   0
#define EH_OFF   17408                 // 64*272
#define ACT0_OFF 34816
#define ACT1_OFF 69632                 // +128*272
#define RED_OFF  104448
#define SMEM_REQ 105472

__device__ __forceinline__ uint32_t smem_to_u32(const void* p) {
    uint32_t a;
    asm("{ .reg .u64 t; cvta.to.shared.u64 t, %1; cvt.u32.u64 %0, t; }" : "=r"(a) : "l"(p));
    return a;
}
__device__ __forceinline__ uint32_t f22h2(float a, float b) {
    __half2 h = __floats2half2_rn(a, b);
    return *reinterpret_cast<uint32_t*>(&h);
}

#define LDSM_X4(r0, r1, r2, r3, addr)                                          \
    asm volatile("ldmatrix.sync.aligned.m8n8.x4.shared.b16 {%0,%1,%2,%3}, [%4];" \
        : "=r"(r0), "=r"(r1), "=r"(r2), "=r"(r3) : "r"(addr))

#define MMA_F16(c, a, b0, b1)                                                  \
    asm volatile("mma.sync.aligned.m16n8k16.row.col.f32.f16.f16.f32 "           \
        "{%0,%1,%2,%3},{%4,%5,%6,%7},{%8,%9},{%0,%1,%2,%3};"                    \
        : "+f"((c)[0]), "+f"((c)[1]), "+f"((c)[2]), "+f"((c)[3])                \
        : "r"((a)[0]), "r"((a)[1]), "r"((a)[2]), "r"((a)[3]), "r"(b0), "r"(b1))

// One K-step of the 64x128 GEMM (4 LDSM + 8 MMA), bBase selects act tile.
#define GEMM_STEP(ks, bBase)                                                    \
    {                                                                           \
        const uint32_t koff = (ks) * 32;                                        \
        uint32_t ah[2][4], bv[2][4];                                            \
        _Pragma("unroll")                                                       \
        for (int mt = 0; mt < 2; mt++)                                          \
            LDSM_X4(ah[mt][0], ah[mt][1], ah[mt][2], ah[mt][3],                 \
                    aBase + mt * (16 * NSTRIDE) + koff);                        \
        _Pragma("unroll")                                                       \
        for (int p = 0; p < 2; p++)                                             \
            LDSM_X4(bv[p][0], bv[p][1], bv[p][2], bv[p][3],                     \
                    (bBase) + p * (16 * NSTRIDE) + koff);                       \
        _Pragma("unroll")                                                       \
        for (int mt = 0; mt < 2; mt++)                                          \
            _Pragma("unroll")                                                   \
            for (int p = 0; p < 2; p++) {                                       \
                MMA_F16(acc[mt][2 * p],     ah[mt], bv[p][0], bv[p][2]);        \
                MMA_F16(acc[mt][2 * p + 1], ah[mt], bv[p][1], bv[p][3]);        \
            }                                                                   \
    }

// Epilogue: rowsum over EhT (smem), quad shuffle. Writes rowsum[2][2].
#define EPILOGUE(rowsum)                                                        \
    _Pragma("unroll")                                                           \
    for (int mt = 0; mt < 2; mt++)                                              \
        _Pragma("unroll")                                                       \
        for (int rh = 0; rh < 2; rh++) {                                        \
            const int nloc = wm * 32 + mt * 16 + rh * 8 + (l >> 2);             \
            const char* eRow = smem + EH_OFF + nloc * NSTRIDE                   \
                             + (wn * 32 + 2 * (l & 3)) * 2;                     \
            float sum_ = 0.0f;                                                  \
            _Pragma("unroll")                                                   \
            for (int nt = 0; nt < 4; nt++) {                                    \
                const float2 ef =                                               \
                    __half22float2(*(const __half2*)(eRow + nt * 16));          \
                sum_ += acc[mt][nt][rh * 2] * ef.x                              \
                      + acc[mt][nt][rh * 2 + 1] * ef.y;                         \
            }                                                                   \
            sum_ += __shfl_xor_sync(0xFFFFFFFF, sum_, 1);                       \
            sum_ += __shfl_xor_sync(0xFFFFFFFF, sum_, 2);                       \
            rowsum[mt][rh] = sum_;                                              \
        }

#define RED_WRITE(rowsum)                                                       \
    if ((l & 3) == 0) {                                                         \
        _Pragma("unroll")                                                       \
        for (int mt = 0; mt < 2; mt++)                                          \
            _Pragma("unroll")                                                   \
            for (int rh = 0; rh < 2; rh++) {                                    \
                const int nloc = wm * 32 + mt * 16 + rh * 8 + (l >> 2);         \
                red[wn * 64 + nloc] = rowsum[mt][rh];                           \
            }                                                                   \
    }

__global__ __launch_bounds__(256, 2) void fused_kernel(
    const float* __restrict__ act,    // [8,128,128]
    const float* __restrict__ mu,     // [4096,2]
    const float* __restrict__ sigma,  // [4096,2]
    float* __restrict__ out)          // [8,4096]
{
    extern __shared__ char smem[];
    const uint32_t sb = smem_to_u32(smem);

    const int tid = threadIdx.x;
    const int wid = tid >> 5, l = tid & 31;
    const int wm = wid & 1;            // n half: rows wm*32..+32
    const int wn = wid >> 1;           // h quarter: cols wn*32..+32
    const int b0 = blockIdx.y * 2;
    const int n0 = blockIdx.x * 64;

    // Table parameters (issue these LDGs early)
    const int en = tid >> 2;                    // table row (local n) 0..63
    const int qd = tid & 3;                     // 32-col quarter
    const float2 m = ((const float2*)mu)[n0 + en];
    const float2 s = ((const float2*)sigma)[n0 + en];

    // ---- Phase A1: act0 -> fp16 smem. 8 chunks/thread, chunk = 16B fp16 ----
    const float4* g0 = (const float4*)(act + b0 * HDIM * HDIM);
    #pragma unroll
    for (int k = 0; k < 8; k++) {
        const int cid = k * 256 + tid;          // 0..2047
        const int r = cid >> 4, u = cid & 15;
        const float4 va = __ldg(&g0[r * 32 + u * 2]);
        const float4 vb = __ldg(&g0[r * 32 + u * 2 + 1]);
        uint4 o;
        o.x = f22h2(va.x, va.y); o.y = f22h2(va.z, va.w);
        o.z = f22h2(vb.x, vb.y); o.w = f22h2(vb.z, vb.w);
        *(uint4*)(smem + ACT0_OFF + r * NSTRIDE + u * 16) = o;
    }

    // ---- Phase A2: EwT + EhT tables (32 __expf each per thread) ------------
    {
        const float invy = 1.0f / (2.0f * s.y * s.y);
        const float invx = 1.0f / (2.0f * s.x * s.x);
        char* rowW = smem + EW_OFF + en * NSTRIDE + qd * 64;
        char* rowH = smem + EH_OFF + en * NSTRIDE + qd * 64;
        const float j0 = (float)(qd * 32) * (1.0f / 128.0f);
        #pragma unroll
        for (int c4 = 0; c4 < 8; c4++) {
            float ew[4], eh[4];
            #pragma unroll
            for (int j = 0; j < 4; j++) {
                const float g = j0 + (float)(c4 * 4 + j) * (1.0f / 128.0f);
                const float dy = g - m.y;
                const float dx = g - m.x;
                ew[j] = __expf(-(dy * dy * invy));
                eh[j] = __expf(-(dx * dx * invx));
            }
            ((__half2*)(rowW + c4 * 8))[0] = __floats2half2_rn(ew[0], ew[1]);
            ((__half2*)(rowW + c4 * 8))[1] = __floats2half2_rn(ew[2], ew[3]);
            ((__half2*)(rowH + c4 * 8))[0] = __floats2half2_rn(eh[0], eh[1]);
            ((__half2*)(rowH + c4 * 8))[1] = __floats2half2_rn(eh[2], eh[3]);
        }
    }
    __syncthreads();

    // ---- Phase B: GEMM0 with act1 staging interleaved ---------------------
    const uint32_t lrow = l & 15, lcol = (l >> 4) * 16;
    const uint32_t aBase  = sb + EW_OFF  + (wm * 32 + lrow) * NSTRIDE + lcol;
    const uint32_t b0Base = sb + ACT0_OFF + (wn * 32 + lrow) * NSTRIDE + lcol;
    const uint32_t b1Base = sb + ACT1_OFF + (wn * 32 + lrow) * NSTRIDE + lcol;
    const float4* g1 = (const float4*)(act + (b0 + 1) * HDIM * HDIM);
    float* red = (float*)(smem + RED_OFF);      // [4 wn][64 n]

    float acc[2][4][4];
    #pragma unroll
    for (int mt = 0; mt < 2; mt++)
        #pragma unroll
        for (int nt = 0; nt < 4; nt++)
            #pragma unroll
            for (int k = 0; k < 4; k++) acc[mt][nt][k] = 0.0f;

    #pragma unroll
    for (int ks = 0; ks < 8; ks++) {
        // issue act1 chunk loads, compute GEMM step, then convert+store
        const int cid = ks * 256 + tid;
        const int r = cid >> 4, u = cid & 15;
        const float4 va = __ldg(&g1[r * 32 + u * 2]);
        const float4 vb = __ldg(&g1[r * 32 + u * 2 + 1]);
        GEMM_STEP(ks, b0Base);
        uint4 o;
        o.x = f22h2(va.x, va.y); o.y = f22h2(va.z, va.w);
        o.z = f22h2(vb.x, vb.y); o.w = f22h2(vb.z, vb.w);
        *(uint4*)(smem + ACT1_OFF + r * NSTRIDE + u * 16) = o;
    }

    // ---- Phase C: epilogue 0 ----------------------------------------------
    float rowsum[2][2];
    EPILOGUE(rowsum);
    RED_WRITE(rowsum);
    __syncthreads();   // red visible; also fences ACT1 STS for GEMM1
    if (tid < 64)
        out[b0 * NPTS + n0 + tid] =
            (red[tid] + red[64 + tid] + red[128 + tid] + red[192 + tid])
            * 6.103515625e-05f;

    // ---- Phase D: GEMM1 ---------------------------------------------------
    #pragma unroll
    for (int mt = 0; mt < 2; mt++)
        #pragma unroll
        for (int nt = 0; nt < 4; nt++)
            #pragma unroll
            for (int k = 0; k < 4; k++) acc[mt][nt][k] = 0.0f;
    #pragma unroll
    for (int ks = 0; ks < 8; ks++)
        GEMM_STEP(ks, b1Base);

    // ---- Phase E: epilogue 1 ----------------------------------------------
    EPILOGUE(rowsum);
    __syncthreads();   // everyone done reading red for out0
    RED_WRITE(rowsum);
    __syncthreads();
    if (tid < 64)
        out[(b0 + 1) * NPTS + n0 + tid] =
            (red[tid] + red[64 + tid] + red[128 + tid] + red[192 + tid])
            * 6.103515625e-05f;
}

// ---------------------------------------------------------------------------
extern "C" void kernel_launch(void* const* d_in, const int* in_sizes, int n_in,
                              void* d_out, int out_size)
{
    const float* act   = (const float*)d_in[0];   // [8,128,128]
    const float* mu    = (const float*)d_in[1];   // [4096,2]
    const float* sigma = (const float*)d_in[2];   // [4096,2]
    float* out = (float*)d_out;                   // [8,64,64]

    cudaFuncSetAttribute(fused_kernel,
                         cudaFuncAttributeMaxDynamicSharedMemorySize, SMEM_REQ);

    fused_kernel<<<dim3(NPTS / 64, 4), 256, SMEM_REQ>>>(act, mu, sigma, out);
}

// round 15
// speedup vs baseline: 1.1688x; 1.0078x over previous
#include <cuda_runtime.h>
#include <cuda_fp16.h>
#include <cstdint>

// Single-launch producer/consumer pipeline:
//   32 producer CTAs (bx 0..31): compute fp16 EwT/EhT tables for one n-tile of
//     128 -> global, threadfence, set flag.
//   256 consumer CTAs (bx 32..287): (n-tile, batch). Stage act (fp32->fp16
//     smem), acquire-poll flag, cp.async tables, GEMM M=128 N=128 K=128
//     (mma.sync.m16n8k16.f16, fp32 accum), smem EhT epilogue.
//   Bounded-spin fallback: consumer computes its own tables (bit-identical
//     __expf sequence) if flag never arrives -> correctness never depends on
//     co-residency. Grid 288 <= 296 slots @2 CTAs/SM -> single wave; producers
//     have the lowest bids so they are placed first.

#define HDIM 128
#define NPTS 4096
#define SPIN_LIMIT 8192

__device__ __align__(256) __half g_EW[NPTS * HDIM];   // EwT [n][w]
__device__ __align__(256) __half g_EH[NPTS * HDIM];   // EhT [n][h]
__device__ int g_flag[32];

#define NSTRIDE  272                   // 17*16 -> conflict-free ldmatrix/LDS
#define EW_OFF   0
#define EH_OFF   34816                 // 128*272
#define ACT_OFF  69632
#define RED_OFF  104448                // 2*128 floats (sFlag reuses word 0 pre-GEMM)
#define SMEM_REQ 105472

__device__ __forceinline__ uint32_t smem_to_u32(const void* p) {
    uint32_t a;
    asm("{ .reg .u64 t; cvta.to.shared.u64 t, %1; cvt.u32.u64 %0, t; }" : "=r"(a) : "l"(p));
    return a;
}
__device__ __forceinline__ uint32_t f22h2(float a, float b) {
    __half2 h = __floats2half2_rn(a, b);
    return *reinterpret_cast<uint32_t*>(&h);
}
#define CP16(dst, src) \
    asm volatile("cp.async.cg.shared.global [%0], [%1], 16;" :: "r"(dst), "l"(src) : "memory")
#define CP_COMMIT() asm volatile("cp.async.commit_group;" ::: "memory")
#define CP_WAIT0()  asm volatile("cp.async.wait_group 0;" ::: "memory")

#define LDSM_X4(r0, r1, r2, r3, addr)                                          \
    asm volatile("ldmatrix.sync.aligned.m8n8.x4.shared.b16 {%0,%1,%2,%3}, [%4];" \
        : "=r"(r0), "=r"(r1), "=r"(r2), "=r"(r3) : "r"(addr))

#define MMA_F16(c, a, b0, b1)                                                  \
    asm volatile("mma.sync.aligned.m16n8k16.row.col.f32.f16.f16.f32 "           \
        "{%0,%1,%2,%3},{%4,%5,%6,%7},{%8,%9},{%0,%1,%2,%3};"                    \
        : "+f"((c)[0]), "+f"((c)[1]), "+f"((c)[2]), "+f"((c)[3])                \
        : "r"((a)[0]), "r"((a)[1]), "r"((a)[2]), "r"((a)[3]), "r"(b0), "r"(b1))

// 8 Gaussian factors starting at g0 (step 1/128), packed to 4x half2.
// IDENTICAL op sequence in producer and fallback -> bit-identical fp16.
__device__ __forceinline__ void gauss8(float g0, float mval, float inv, uint4* o)
{
    float e[8];
    #pragma unroll
    for (int j = 0; j < 8; j++) {
        const float d = g0 + (float)j * (1.0f / 128.0f) - mval;
        e[j] = __expf(-(d * d * inv));
    }
    o->x = f22h2(e[0], e[1]); o->y = f22h2(e[2], e[3]);
    o->z = f22h2(e[4], e[5]); o->w = f22h2(e[6], e[7]);
}

__global__ __launch_bounds__(256, 2) void pc_kernel(
    const float* __restrict__ act,    // [8,128,128]
    const float* __restrict__ mu,     // [4096,2]
    const float* __restrict__ sigma,  // [4096,2]
    float* __restrict__ out)          // [8,4096]
{
    extern __shared__ char smem[];
    const uint32_t sb = smem_to_u32(smem);
    const int tid = threadIdx.x;
    const int bx  = blockIdx.x;

    // ======================= PRODUCER (bx < 32) ============================
    if (bx < 32) {
        const int nt = bx, n0 = nt << 7;
        const int en = tid >> 1;              // row (local n) 0..127
        const int c0 = (tid & 1) * 64;        // col start
        const float2 m = ((const float2*)mu)[n0 + en];
        const float2 s = ((const float2*)sigma)[n0 + en];
        const float invy = 1.0f / (2.0f * s.y * s.y);
        const float invx = 1.0f / (2.0f * s.x * s.x);
        uint4* dW = (uint4*)(g_EW + (n0 + en) * HDIM + c0);
        uint4* dH = (uint4*)(g_EH + (n0 + en) * HDIM + c0);
        #pragma unroll
        for (int grp = 0; grp < 8; grp++) {
            const float g0 = (float)(c0 + grp * 8) * (1.0f / 128.0f);
            uint4 ow, oh;
            gauss8(g0, m.y, invy, &ow);
            gauss8(g0, m.x, invx, &oh);
            dW[grp] = ow;
            dH[grp] = oh;
        }
        __syncthreads();
        __threadfence();
        if (tid == 0) atomicExch(&g_flag[nt], 1);
        return;
    }

    // ======================= CONSUMER ======================================
    const int idx = bx - 32;
    const int nt = idx & 31, b = idx >> 5;
    const int n0 = nt << 7;
    const int wid = tid >> 5, l = tid & 31;
    const int wm = wid & 3;            // n block of 32
    const int wn = wid >> 2;           // h half of 64

    // ---- Stage act: 8 chunks/thread (LDG 2x float4 -> 16B fp16 STS) -------
    const float4* g0p = (const float4*)(act + b * HDIM * HDIM);
    #pragma unroll
    for (int k = 0; k < 8; k++) {
        const int cid = k * 256 + tid;        // 0..2047
        const int r = cid >> 4, u = cid & 15;
        const float4 va = __ldg(&g0p[r * 32 + u * 2]);
        const float4 vb = __ldg(&g0p[r * 32 + u * 2 + 1]);
        uint4 o;
        o.x = f22h2(va.x, va.y); o.y = f22h2(va.z, va.w);
        o.z = f22h2(vb.x, vb.y); o.w = f22h2(vb.z, vb.w);
        *(uint4*)(smem + ACT_OFF + r * NSTRIDE + u * 16) = o;
    }

    // ---- Wait for producer (bounded; fallback keeps correctness) ----------
    volatile int* sFlag = (volatile int*)(smem + RED_OFF);
    if (tid == 0) {
        int ok = 0;
        for (int it = 0; it < SPIN_LIMIT; it++) {
            int f;
            asm volatile("ld.acquire.gpu.global.b32 %0, [%1];"
                         : "=r"(f) : "l"(&g_flag[nt]) : "memory");
            if (f) { ok = 1; break; }
        }
        *sFlag = ok;
    }
    __syncthreads();
    const int have_tables = *sFlag;
    __syncthreads();

    if (have_tables) {
        // cp.async the two tables: 8 chunks each per thread
        const __half* gW = g_EW + n0 * HDIM;
        const __half* gH = g_EH + n0 * HDIM;
        #pragma unroll
        for (int k = 0; k < 8; k++) {
            const int cid = k * 256 + tid;
            const int r = cid >> 4, u = cid & 15;
            const uint32_t d = r * NSTRIDE + u * 16;
            const int so = r * HDIM + u * 8;
            CP16(sb + EW_OFF + d, gW + so);
            CP16(sb + EH_OFF + d, gH + so);
        }
        CP_COMMIT();
        CP_WAIT0();
    } else {
        // Fallback: compute tables locally (bit-identical to producer)
        const int en = tid >> 1, c0 = (tid & 1) * 64;
        const float2 m = ((const float2*)mu)[n0 + en];
        const float2 s = ((const float2*)sigma)[n0 + en];
        const float invy = 1.0f / (2.0f * s.y * s.y);
        const float invx = 1.0f / (2.0f * s.x * s.x);
        #pragma unroll
        for (int grp = 0; grp < 8; grp++) {
            const float gg = (float)(c0 + grp * 8) * (1.0f / 128.0f);
            uint4 ow, oh;
            gauss8(gg, m.y, invy, &ow);
            gauss8(gg, m.x, invx, &oh);
            *(uint4*)(smem + EW_OFF + en * NSTRIDE + (c0 + grp * 8) * 2) = ow;
            *(uint4*)(smem + EH_OFF + en * NSTRIDE + (c0 + grp * 8) * 2) = oh;
        }
    }
    __syncthreads();

    // ---- GEMM: M=128(n) x N=128(h) x K=128(w), warp tile 32n x 64h --------
    const uint32_t lrow = l & 15, lcol = (l >> 4) * 16;
    const uint32_t aBase = sb + EW_OFF + (wm * 32 + lrow) * NSTRIDE + lcol;
    const uint32_t bBase = sb + ACT_OFF + (wn * 64 + lrow) * NSTRIDE + lcol;

    float acc[2][8][4];
    #pragma unroll
    for (int mt = 0; mt < 2; mt++)
        #pragma unroll
        for (int nt2 = 0; nt2 < 8; nt2++)
            #pragma unroll
            for (int k = 0; k < 4; k++) acc[mt][nt2][k] = 0.0f;

    #pragma unroll
    for (int ks = 0; ks < 8; ks++) {
        const uint32_t koff = ks * 32;
        uint32_t ah[2][4], bv[4][4];
        #pragma unroll
        for (int mt = 0; mt < 2; mt++)
            LDSM_X4(ah[mt][0], ah[mt][1], ah[mt][2], ah[mt][3],
                    aBase + mt * (16 * NSTRIDE) + koff);
        #pragma unroll
        for (int p = 0; p < 4; p++)
            LDSM_X4(bv[p][0], bv[p][1], bv[p][2], bv[p][3],
                    bBase + p * (16 * NSTRIDE) + koff);
        #pragma unroll
        for (int mt = 0; mt < 2; mt++)
            #pragma unroll
            for (int p = 0; p < 4; p++) {
                MMA_F16(acc[mt][2 * p],     ah[mt], bv[p][0], bv[p][2]);
                MMA_F16(acc[mt][2 * p + 1], ah[mt], bv[p][1], bv[p][3]);
            }
    }

    // ---- Epilogue: EhT from smem, quad shuffle, cross-warp reduce ---------
    // D rows: nloc = wm*32 + mt*16 + rh*8 + l/4; cols h = wn*64 + nt2*8 + 2(l&3)+{0,1}
    float rowsum[2][2];
    #pragma unroll
    for (int mt = 0; mt < 2; mt++)
        #pragma unroll
        for (int rh = 0; rh < 2; rh++) {
            const int nloc = wm * 32 + mt * 16 + rh * 8 + (l >> 2);
            const char* eRow = smem + EH_OFF + nloc * NSTRIDE
                             + (wn * 64 + 2 * (l & 3)) * 2;
            float s = 0.0f;
            #pragma unroll
            for (int nt2 = 0; nt2 < 8; nt2++) {
                const float2 ef = __half22float2(*(const __half2*)(eRow + nt2 * 16));
                s += acc[mt][nt2][rh * 2] * ef.x + acc[mt][nt2][rh * 2 + 1] * ef.y;
            }
            s += __shfl_xor_sync(0xFFFFFFFF, s, 1);
            s += __shfl_xor_sync(0xFFFFFFFF, s, 2);
            rowsum[mt][rh] = s;
        }

    __syncthreads();                 // sFlag word dead; red buffer reusable
    float* red = (float*)(smem + RED_OFF);      // [2 wn][128 n]
    if ((l & 3) == 0) {
        #pragma unroll
        for (int mt = 0; mt < 2; mt++)
            #pragma unroll
            for (int rh = 0; rh < 2; rh++) {
                const int nloc = wm * 32 + mt * 16 + rh * 8 + (l >> 2);
                red[wn * 128 + nloc] = rowsum[mt][rh];
            }
    }
    __syncthreads();
    if (tid < 128)
        out[b * NPTS + n0 + tid] =
            (red[tid] + red[128 + tid]) * 6.103515625e-05f;  // 1/16384
}

// ---------------------------------------------------------------------------
extern "C" void kernel_launch(void* const* d_in, const int* in_sizes, int n_in,
                              void* d_out, int out_size)
{
    const float* act   = (const float*)d_in[0];   // [8,128,128]
    const float* mu    = (const float*)d_in[1];   // [4096,2]
    const float* sigma = (const float*)d_in[2];   // [4096,2]
    float* out = (float*)d_out;                   // [8,64,64]

    cudaFuncSetAttribute(pc_kernel,
                         cudaFuncAttributeMaxDynamicSharedMemorySize, SMEM_REQ);

    pc_kernel<<<288, 256, SMEM_REQ>>>(act, mu, sigma, out);
}